// round 1
// baseline (speedup 1.0000x reference)
#include <cuda_runtime.h>
#include <math.h>

#define B_  8
#define L_  128
#define H_  768
#define M_  (B_ * L_)      // 1024 rows
#define LL_ (L_ * L_)      // 16384 pairs per batch

// ---------------- scratch (no allocations allowed) ----------------
__device__ float g_A[M_ * H_];          // seq @ W1[:H] + b1   (3 MB)
__device__ float g_C[M_ * H_];          // seq @ W1[H:]        (3 MB)
__device__ float g_se[2 * M_];          // per-row start/end CE
__device__ float g_span_partial[128];   // per-block span BCE partials

// ---------------- exact GELU: erf via A&S 7.1.26 (|eps| <= 1.5e-7) ----------
__device__ __forceinline__ float gelu_exact(float x) {
    float ax = fabsf(x);
    float z  = 0.70710678118654752f * ax;           // |x|/sqrt(2)
    float t  = __fdividef(1.0f, fmaf(0.3275911f, z, 1.0f));
    float p  = fmaf(1.061405429f, t, -1.453152027f);
    p = fmaf(p, t, 1.421413741f);
    p = fmaf(p, t, -0.284496736f);
    p = fmaf(p, t, 0.254829592f);
    p = p * t;
    float e      = __expf(-z * z);
    float erf_ax = fmaf(-p, e, 1.0f);
    float erf_x  = copysignf(erf_ax, x);
    float hx     = 0.5f * x;
    return fmaf(hx, erf_x, hx);                     // 0.5*x*(1+erf(x/sqrt2))
}

// ---------------- fused GEMM: [A|C] = seq(1024x768) @ W1-derived (768x1536) ---
// out col n < 768 :  A[m,n] = sum_k seq[m,k]*W1[k*768+n]       (+ b1[n])
// out col n >= 768:  C[m,n-768] = sum_k seq[m,k]*W1[(768+k)*768+(n-768)]
__global__ void __launch_bounds__(256) gemm_kernel(
    const float* __restrict__ seq, const float* __restrict__ W1,
    const float* __restrict__ b1)
{
    __shared__ float As[16][68];   // k-major, padded (row stride 272B, 16B aligned)
    __shared__ float Bs[16][64];

    int tid = threadIdx.x;
    int tx = tid & 15, ty = tid >> 4;
    int m0 = blockIdx.y << 6;           // 16 tiles
    int n0 = blockIdx.x << 6;           // 24 tiles
    int isC = (n0 >= H_);
    const float* Bbase = W1 + (isC ? (H_ * H_ + (n0 - H_)) : n0);

    int a_row = tid >> 2;               // 0..63
    int a_k4  = (tid & 3) << 2;         // 0,4,8,12
    int b_k   = tid >> 4;               // 0..15
    int b_n4  = (tid & 15) << 2;        // 0..60

    float acc[4][4];
#pragma unroll
    for (int r = 0; r < 4; r++)
#pragma unroll
        for (int c = 0; c < 4; c++) acc[r][c] = 0.0f;

    for (int k0 = 0; k0 < H_; k0 += 16) {
        float4 av = *(const float4*)(seq + (m0 + a_row) * H_ + k0 + a_k4);
        As[a_k4 + 0][a_row] = av.x;
        As[a_k4 + 1][a_row] = av.y;
        As[a_k4 + 2][a_row] = av.z;
        As[a_k4 + 3][a_row] = av.w;
        *(float4*)(&Bs[b_k][b_n4]) = *(const float4*)(Bbase + (k0 + b_k) * H_ + b_n4);
        __syncthreads();
#pragma unroll
        for (int k = 0; k < 16; k++) {
            float4 a  = *(const float4*)(&As[k][ty << 2]);
            float4 bb = *(const float4*)(&Bs[k][tx << 2]);
            acc[0][0] = fmaf(a.x, bb.x, acc[0][0]);
            acc[0][1] = fmaf(a.x, bb.y, acc[0][1]);
            acc[0][2] = fmaf(a.x, bb.z, acc[0][2]);
            acc[0][3] = fmaf(a.x, bb.w, acc[0][3]);
            acc[1][0] = fmaf(a.y, bb.x, acc[1][0]);
            acc[1][1] = fmaf(a.y, bb.y, acc[1][1]);
            acc[1][2] = fmaf(a.y, bb.z, acc[1][2]);
            acc[1][3] = fmaf(a.y, bb.w, acc[1][3]);
            acc[2][0] = fmaf(a.z, bb.x, acc[2][0]);
            acc[2][1] = fmaf(a.z, bb.y, acc[2][1]);
            acc[2][2] = fmaf(a.z, bb.z, acc[2][2]);
            acc[2][3] = fmaf(a.z, bb.w, acc[2][3]);
            acc[3][0] = fmaf(a.w, bb.x, acc[3][0]);
            acc[3][1] = fmaf(a.w, bb.y, acc[3][1]);
            acc[3][2] = fmaf(a.w, bb.z, acc[3][2]);
            acc[3][3] = fmaf(a.w, bb.w, acc[3][3]);
        }
        __syncthreads();
    }

    int nc = n0 + (tx << 2);
    float4 badd = make_float4(0.f, 0.f, 0.f, 0.f);
    if (!isC) badd = *(const float4*)(b1 + nc);
#pragma unroll
    for (int r = 0; r < 4; r++) {
        int m = m0 + (ty << 2) + r;
        float4 o;
        o.x = acc[r][0] + badd.x;
        o.y = acc[r][1] + badd.y;
        o.z = acc[r][2] + badd.z;
        o.w = acc[r][3] + badd.w;
        if (!isC) *(float4*)(g_A + m * H_ + nc) = o;
        else      *(float4*)(g_C + m * H_ + (nc - H_)) = o;
    }
}

// ---------------- start/end CE: one block per token row ----------------
__global__ void __launch_bounds__(128) se_kernel(
    const float* __restrict__ seq,
    const float* __restrict__ Ws, const float* __restrict__ bs,
    const float* __restrict__ We, const float* __restrict__ be,
    const int* __restrict__ spos, const int* __restrict__ epos)
{
    int m = blockIdx.x;
    int tid = threadIdx.x;
    const float* row = seq + m * H_;
    float s0 = 0.f, s1 = 0.f, e0 = 0.f, e1 = 0.f;
    for (int h = tid; h < H_; h += 128) {
        float x = row[h];
        s0 = fmaf(x, Ws[2 * h], s0);
        s1 = fmaf(x, Ws[2 * h + 1], s1);
        e0 = fmaf(x, We[2 * h], e0);
        e1 = fmaf(x, We[2 * h + 1], e1);
    }
#pragma unroll
    for (int o = 16; o; o >>= 1) {
        s0 += __shfl_down_sync(0xffffffffu, s0, o);
        s1 += __shfl_down_sync(0xffffffffu, s1, o);
        e0 += __shfl_down_sync(0xffffffffu, e0, o);
        e1 += __shfl_down_sync(0xffffffffu, e1, o);
    }
    __shared__ float buf[4][4];
    int w = tid >> 5, lane = tid & 31;
    if (lane == 0) { buf[w][0] = s0; buf[w][1] = s1; buf[w][2] = e0; buf[w][3] = e1; }
    __syncthreads();
    if (tid == 0) {
        s0 = buf[0][0] + buf[1][0] + buf[2][0] + buf[3][0] + bs[0];
        s1 = buf[0][1] + buf[1][1] + buf[2][1] + buf[3][1] + bs[1];
        e0 = buf[0][2] + buf[1][2] + buf[2][2] + buf[3][2] + be[0];
        e1 = buf[0][3] + buf[1][3] + buf[2][3] + buf[3][3] + be[1];
        float mx  = fmaxf(s0, s1);
        float lse = mx + logf(expf(s0 - mx) + expf(s1 - mx));
        g_se[m] = lse - (spos[m] ? s1 : s0);
        mx  = fmaxf(e0, e1);
        lse = mx + logf(expf(e0 - mx) + expf(e1 - mx));
        g_se[M_ + m] = lse - (epos[m] ? e1 : e0);
    }
}

// ---------------- span BCE: 32x32 (i,j) tile per block, h staged in smem ------
__global__ void __launch_bounds__(256) span_kernel(
    const int* __restrict__ spanp, const float* __restrict__ w2,
    const float* __restrict__ b2)
{
    __shared__ float sA[32][65];
    __shared__ float sC[32][65];
    __shared__ float sW[64];
    __shared__ float red[256];

    int tid = threadIdx.x;
    int tx = tid & 15, ty = tid >> 4;
    int b = blockIdx.z;
    int i0 = blockIdx.y << 5;
    int j0 = blockIdx.x << 5;
    const float* Abase = g_A + (b * L_ + i0) * H_;
    const float* Cbase = g_C + (b * L_ + j0) * H_;

    float acc00 = 0.f, acc01 = 0.f, acc10 = 0.f, acc11 = 0.f;
    int il = ty << 1, jl = tx << 1;

    for (int hc = 0; hc < H_; hc += 64) {
#pragma unroll
        for (int r = 0; r < 2; r++) {
            int q   = tid + (r << 8);
            int row = q >> 4;            // 0..31
            int c4  = (q & 15) << 2;     // 0..60
            float4 va = *(const float4*)(Abase + row * H_ + hc + c4);
            sA[row][c4 + 0] = va.x; sA[row][c4 + 1] = va.y;
            sA[row][c4 + 2] = va.z; sA[row][c4 + 3] = va.w;
            float4 vc = *(const float4*)(Cbase + row * H_ + hc + c4);
            sC[row][c4 + 0] = vc.x; sC[row][c4 + 1] = vc.y;
            sC[row][c4 + 2] = vc.z; sC[row][c4 + 3] = vc.w;
        }
        if (tid < 64) sW[tid] = w2[hc + tid];
        __syncthreads();
#pragma unroll 4
        for (int h = 0; h < 64; h++) {
            float wv = sW[h];
            float a0 = sA[il][h],     a1 = sA[il + 1][h];
            float c0 = sC[jl][h],     c1 = sC[jl + 1][h];
            acc00 = fmaf(gelu_exact(a0 + c0), wv, acc00);
            acc01 = fmaf(gelu_exact(a0 + c1), wv, acc01);
            acc10 = fmaf(gelu_exact(a1 + c0), wv, acc10);
            acc11 = fmaf(gelu_exact(a1 + c1), wv, acc11);
        }
        __syncthreads();
    }

    float b2v = b2[0];
    const int* zb = spanp + b * LL_;
    int i = i0 + il, j = j0 + jl;
    float lg[2][2] = {{acc00, acc01}, {acc10, acc11}};
    float bsum = 0.f;
#pragma unroll
    for (int r = 0; r < 2; r++)
#pragma unroll
        for (int s = 0; s < 2; s++) {
            float sg = lg[r][s] + b2v;
            float z  = (float)zb[(i + r) * L_ + (j + s)];
            bsum += fmaxf(sg, 0.f) - sg * z + log1pf(__expf(-fabsf(sg)));
        }

    red[tid] = bsum;
    __syncthreads();
    for (int o = 128; o; o >>= 1) {
        if (tid < o) red[tid] += red[tid + o];
        __syncthreads();
    }
    if (tid == 0)
        g_span_partial[(blockIdx.z << 4) + (blockIdx.y << 2) + blockIdx.x] = red[0];
}

// ---------------- final deterministic reduction ----------------
__global__ void __launch_bounds__(256) final_kernel(float* __restrict__ out)
{
    __shared__ float red[256];
    int tid = threadIdx.x;
    float se = 0.f;
    for (int i = tid; i < 2 * M_; i += 256) se += g_se[i];
    float sp = 0.f;
    if (tid < 128) sp = g_span_partial[tid];
    red[tid] = se * (1.0f / (float)M_) + sp * (1.0f / (float)(B_ * LL_));
    __syncthreads();
    for (int o = 128; o; o >>= 1) {
        if (tid < o) red[tid] += red[tid + o];
        __syncthreads();
    }
    if (tid == 0) out[0] = red[0];
}

// ---------------- launch ----------------
extern "C" void kernel_launch(void* const* d_in, const int* in_sizes, int n_in,
                              void* d_out, int out_size)
{
    const float* seq   = (const float*)d_in[0];
    const int*   spos  = (const int*)  d_in[1];
    const int*   epos  = (const int*)  d_in[2];
    const int*   spanp = (const int*)  d_in[3];
    const float* Ws    = (const float*)d_in[4];
    const float* bs    = (const float*)d_in[5];
    const float* We    = (const float*)d_in[6];
    const float* be    = (const float*)d_in[7];
    const float* W1    = (const float*)d_in[8];
    const float* b1    = (const float*)d_in[9];
    const float* w2    = (const float*)d_in[10];
    const float* b2    = (const float*)d_in[11];
    float* out = (float*)d_out;

    gemm_kernel<<<dim3(24, 16), 256>>>(seq, W1, b1);
    se_kernel<<<M_, 128>>>(seq, Ws, bs, We, be, spos, epos);
    span_kernel<<<dim3(4, 4, 8), 256>>>(spanp, w2, b2);
    final_kernel<<<1, 256>>>(out);
}

// round 3
// speedup vs baseline: 1.0849x; 1.0849x over previous
#include <cuda_runtime.h>
#include <math.h>

#define B_  8
#define L_  128
#define H_  768
#define M_  (B_ * L_)      // 1024 rows
#define LL_ (L_ * L_)      // 16384 pairs per batch

// ---------------- scratch (no allocations allowed) ----------------
__device__ float g_A[M_ * H_];          // seq @ W1[:H] + b1   (3 MB)
__device__ float g_C[M_ * H_];          // seq @ W1[H:]        (3 MB)
__device__ float g_se[2 * M_];          // per-row start/end CE
__device__ float g_span_partial[128];   // per-block span BCE partials
__device__ unsigned int g_counter;      // last-block counter (self-resetting)

// ---------------- f32x2 packed helpers ----------------
typedef unsigned long long ull;

__device__ __forceinline__ ull dup2(float v) {
    ull r; asm("mov.b64 %0, {%1, %2};" : "=l"(r) : "f"(v), "f"(v)); return r;
}
__device__ __forceinline__ ull pk2(float lo, float hi) {
    ull r; asm("mov.b64 %0, {%1, %2};" : "=l"(r) : "f"(lo), "f"(hi)); return r;
}
__device__ __forceinline__ void upk2(ull v, float& lo, float& hi) {
    asm("mov.b64 {%0, %1}, %2;" : "=f"(lo), "=f"(hi) : "l"(v));
}
__device__ __forceinline__ ull fma2_(ull a, ull b, ull c) {
    ull d; asm("fma.rn.f32x2 %0, %1, %2, %3;" : "=l"(d) : "l"(a), "l"(b), "l"(c)); return d;
}
__device__ __forceinline__ ull mul2_(ull a, ull b) {
    ull d; asm("mul.rn.f32x2 %0, %1, %2;" : "=l"(d) : "l"(a), "l"(b)); return d;
}
__device__ __forceinline__ ull add2_(ull a, ull b) {
    ull d; asm("add.rn.f32x2 %0, %1, %2;" : "=l"(d) : "l"(a), "l"(b)); return d;
}
__device__ __forceinline__ float rcp_(float x) {
    float r; asm("rcp.approx.f32 %0, %1;" : "=f"(r) : "f"(x)); return r;
}
__device__ __forceinline__ float ex2_(float x) {
    float r; asm("ex2.approx.f32 %0, %1;" : "=f"(r) : "f"(x)); return r;
}

// packed exact-GELU (A&S 7.1.26 erf, coefficients sign-flipped so the poly
// yields -p and erf = fma(pn, e, 1); numerically identical to scalar version)
__device__ __forceinline__ ull gelu2(ull x) {
    ull ax  = x & 0x7FFFFFFF7FFFFFFFULL;
    ull sgn = x & 0x8000000080000000ULL;
    ull z = mul2_(ax, dup2(0.70710678118654752f));
    ull d = fma2_(dup2(0.3275911f), z, dup2(1.0f));
    float dl, dh; upk2(d, dl, dh);
    ull t = pk2(rcp_(dl), rcp_(dh));
    ull p = fma2_(dup2(-1.061405429f), t, dup2(1.453152027f));
    p = fma2_(p, t, dup2(-1.421413741f));
    p = fma2_(p, t, dup2(0.284496736f));
    p = fma2_(p, t, dup2(-0.254829592f));
    p = mul2_(p, t);                                   // pn = -p
    ull zz  = mul2_(z, z);
    ull arg = mul2_(zz, dup2(-1.4426950408889634f));   // -z^2 * log2(e)
    float al, ah; upk2(arg, al, ah);
    ull e = pk2(ex2_(al), ex2_(ah));
    ull erf = fma2_(p, e, dup2(1.0f));                 // in (0,1], sign bit 0
    erf |= sgn;                                        // copysign
    ull hx = mul2_(x, dup2(0.5f));
    return fma2_(hx, erf, hx);
}

// ---------------- fused GEMM: [A|C] = seq(1024x768) @ W1-derived (768x1536) ---
__global__ void __launch_bounds__(256) gemm_kernel(
    const float* __restrict__ seq, const float* __restrict__ W1,
    const float* __restrict__ b1)
{
    __shared__ float As[16][68];   // k-major, padded
    __shared__ float Bs[16][64];

    int tid = threadIdx.x;
    int tx = tid & 15, ty = tid >> 4;
    int m0 = blockIdx.y << 6;           // 16 tiles
    int n0 = blockIdx.x << 6;           // 24 tiles
    int isC = (n0 >= H_);
    const float* Bbase = W1 + (isC ? (H_ * H_ + (n0 - H_)) : n0);

    int a_row = tid >> 2;               // 0..63
    int a_k4  = (tid & 3) << 2;         // 0,4,8,12
    int b_k   = tid >> 4;               // 0..15
    int b_n4  = (tid & 15) << 2;        // 0..60

    // reset last-block counter for span kernel (gemm always runs first)
    if (blockIdx.x == 0 && blockIdx.y == 0 && tid == 0) g_counter = 0u;

    ull accP[4][2];
#pragma unroll
    for (int r = 0; r < 4; r++) { accP[r][0] = 0ULL; accP[r][1] = 0ULL; }

    for (int k0 = 0; k0 < H_; k0 += 16) {
        float4 av = *(const float4*)(seq + (m0 + a_row) * H_ + k0 + a_k4);
        As[a_k4 + 0][a_row] = av.x;
        As[a_k4 + 1][a_row] = av.y;
        As[a_k4 + 2][a_row] = av.z;
        As[a_k4 + 3][a_row] = av.w;
        *(float4*)(&Bs[b_k][b_n4]) = *(const float4*)(Bbase + (k0 + b_k) * H_ + b_n4);
        __syncthreads();
#pragma unroll
        for (int k = 0; k < 16; k++) {
            float4 a = *(const float4*)(&As[k][ty << 2]);
            ulonglong2 bp = *(const ulonglong2*)(&Bs[k][tx << 2]);
            ull ad0 = dup2(a.x), ad1 = dup2(a.y), ad2 = dup2(a.z), ad3 = dup2(a.w);
            accP[0][0] = fma2_(ad0, bp.x, accP[0][0]);
            accP[0][1] = fma2_(ad0, bp.y, accP[0][1]);
            accP[1][0] = fma2_(ad1, bp.x, accP[1][0]);
            accP[1][1] = fma2_(ad1, bp.y, accP[1][1]);
            accP[2][0] = fma2_(ad2, bp.x, accP[2][0]);
            accP[2][1] = fma2_(ad2, bp.y, accP[2][1]);
            accP[3][0] = fma2_(ad3, bp.x, accP[3][0]);
            accP[3][1] = fma2_(ad3, bp.y, accP[3][1]);
        }
        __syncthreads();
    }

    int nc = n0 + (tx << 2);
    float4 badd = make_float4(0.f, 0.f, 0.f, 0.f);
    if (!isC) badd = *(const float4*)(b1 + nc);
#pragma unroll
    for (int r = 0; r < 4; r++) {
        int m = m0 + (ty << 2) + r;
        float4 o;
        float c0, c1, c2, c3;
        upk2(accP[r][0], c0, c1);
        upk2(accP[r][1], c2, c3);
        o.x = c0 + badd.x;
        o.y = c1 + badd.y;
        o.z = c2 + badd.z;
        o.w = c3 + badd.w;
        if (!isC) *(float4*)(g_A + m * H_ + nc) = o;
        else      *(float4*)(g_C + m * H_ + (nc - H_)) = o;
    }
}

// ---------------- start/end CE: one block per token row ----------------
__global__ void __launch_bounds__(128) se_kernel(
    const float* __restrict__ seq,
    const float* __restrict__ Ws, const float* __restrict__ bs,
    const float* __restrict__ We, const float* __restrict__ be,
    const int* __restrict__ spos, const int* __restrict__ epos)
{
    int m = blockIdx.x;
    int tid = threadIdx.x;
    const float* row = seq + m * H_;
    float s0 = 0.f, s1 = 0.f, e0 = 0.f, e1 = 0.f;
    for (int h = tid; h < H_; h += 128) {
        float x = row[h];
        float2 ws = *(const float2*)(Ws + 2 * h);
        float2 we = *(const float2*)(We + 2 * h);
        s0 = fmaf(x, ws.x, s0);
        s1 = fmaf(x, ws.y, s1);
        e0 = fmaf(x, we.x, e0);
        e1 = fmaf(x, we.y, e1);
    }
#pragma unroll
    for (int o = 16; o; o >>= 1) {
        s0 += __shfl_down_sync(0xffffffffu, s0, o);
        s1 += __shfl_down_sync(0xffffffffu, s1, o);
        e0 += __shfl_down_sync(0xffffffffu, e0, o);
        e1 += __shfl_down_sync(0xffffffffu, e1, o);
    }
    __shared__ float buf[4][4];
    int w = tid >> 5, lane = tid & 31;
    if (lane == 0) { buf[w][0] = s0; buf[w][1] = s1; buf[w][2] = e0; buf[w][3] = e1; }
    __syncthreads();
    if (tid == 0) {
        s0 = buf[0][0] + buf[1][0] + buf[2][0] + buf[3][0] + bs[0];
        s1 = buf[0][1] + buf[1][1] + buf[2][1] + buf[3][1] + bs[1];
        e0 = buf[0][2] + buf[1][2] + buf[2][2] + buf[3][2] + be[0];
        e1 = buf[0][3] + buf[1][3] + buf[2][3] + buf[3][3] + be[1];
        float mx  = fmaxf(s0, s1);
        float lse = mx + logf(expf(s0 - mx) + expf(s1 - mx));
        g_se[m] = lse - (spos[m] ? s1 : s0);
        mx  = fmaxf(e0, e1);
        lse = mx + logf(expf(e0 - mx) + expf(e1 - mx));
        g_se[M_ + m] = lse - (epos[m] ? e1 : e0);
    }
}

// ---------------- span BCE: 32x32 (i,j) tile, packed gelu over i-pairs --------
__global__ void __launch_bounds__(256) span_kernel(
    const int* __restrict__ spanp, const float* __restrict__ w2,
    const float* __restrict__ b2, float* __restrict__ out)
{
    __shared__ float sAt[64][34];  // TRANSPOSED: [h][i], even stride -> 8B-aligned pairs
    __shared__ float sC[32][65];   // [j][h]
    __shared__ float sW[64];
    __shared__ float red[256];
    __shared__ int   isLast;

    int tid = threadIdx.x;
    int tx = tid & 15, ty = tid >> 4;
    int b = blockIdx.z;
    int i0 = blockIdx.y << 5;
    int j0 = blockIdx.x << 5;
    const float* Abase = g_A + (b * L_ + i0) * H_;
    const float* Cbase = g_C + (b * L_ + j0) * H_;

    int il = ty << 1, jl = tx << 1;
    ull acc0 = 0ULL, acc1 = 0ULL;   // (i0,i1) packed, for j0 / j1

    for (int hc = 0; hc < H_; hc += 64) {
#pragma unroll
        for (int r = 0; r < 2; r++) {
            int q   = tid + (r << 8);
            int row = q >> 4;            // 0..31
            int c4  = (q & 15) << 2;     // 0..60
            float4 va = *(const float4*)(Abase + row * H_ + hc + c4);
            sAt[c4 + 0][row] = va.x;     // transpose A
            sAt[c4 + 1][row] = va.y;
            sAt[c4 + 2][row] = va.z;
            sAt[c4 + 3][row] = va.w;
            float4 vc = *(const float4*)(Cbase + row * H_ + hc + c4);
            sC[row][c4 + 0] = vc.x; sC[row][c4 + 1] = vc.y;
            sC[row][c4 + 2] = vc.z; sC[row][c4 + 3] = vc.w;
        }
        if (tid < 64) sW[tid] = w2[hc + tid];
        __syncthreads();
#pragma unroll 4
        for (int h = 0; h < 64; h++) {
            ull aP = *(const ull*)(&sAt[h][il]);   // (a_i0, a_i1)
            float c0 = sC[jl][h];
            float c1 = sC[jl + 1][h];
            ull wd = dup2(sW[h]);
            ull x0 = add2_(aP, dup2(c0));
            ull x1 = add2_(aP, dup2(c1));
            acc0 = fma2_(gelu2(x0), wd, acc0);
            acc1 = fma2_(gelu2(x1), wd, acc1);
        }
        __syncthreads();
    }

    float b2v = b2[0];
    const int* zb = spanp + b * LL_;
    int i = i0 + il, j = j0 + jl;
    float lg[2][2];
    upk2(acc0, lg[0][0], lg[1][0]);   // (i0,j0), (i1,j0)
    upk2(acc1, lg[0][1], lg[1][1]);   // (i0,j1), (i1,j1)
    float bsum = 0.f;
#pragma unroll
    for (int r = 0; r < 2; r++)
#pragma unroll
        for (int s = 0; s < 2; s++) {
            float sg = lg[r][s] + b2v;
            float z  = (float)zb[(i + r) * L_ + (j + s)];
            bsum += fmaxf(sg, 0.f) - sg * z + log1pf(__expf(-fabsf(sg)));
        }

    red[tid] = bsum;
    __syncthreads();
    for (int o = 128; o; o >>= 1) {
        if (tid < o) red[tid] += red[tid + o];
        __syncthreads();
    }
    int bid = (blockIdx.z << 4) + (blockIdx.y << 2) + blockIdx.x;
    if (tid == 0) {
        g_span_partial[bid] = red[0];
        __threadfence();
        unsigned int old = atomicAdd(&g_counter, 1u);
        isLast = (old == 127u);
    }
    __syncthreads();

    if (isLast) {
        __threadfence();
        float se = 0.f;
        for (int q = tid; q < 2 * M_; q += 256) se += g_se[q];
        float sp = (tid < 128) ? g_span_partial[tid] : 0.f;
        red[tid] = se * (1.0f / (float)M_) + sp * (1.0f / (float)(B_ * LL_));
        __syncthreads();
        for (int o = 128; o; o >>= 1) {
            if (tid < o) red[tid] += red[tid + o];
            __syncthreads();
        }
        if (tid == 0) { out[0] = red[0]; g_counter = 0u; }
    }
}

// ---------------- launch ----------------
extern "C" void kernel_launch(void* const* d_in, const int* in_sizes, int n_in,
                              void* d_out, int out_size)
{
    const float* seq   = (const float*)d_in[0];
    const int*   spos  = (const int*)  d_in[1];
    const int*   epos  = (const int*)  d_in[2];
    const int*   spanp = (const int*)  d_in[3];
    const float* Ws    = (const float*)d_in[4];
    const float* bs    = (const float*)d_in[5];
    const float* We    = (const float*)d_in[6];
    const float* be    = (const float*)d_in[7];
    const float* W1    = (const float*)d_in[8];
    const float* b1    = (const float*)d_in[9];
    const float* w2    = (const float*)d_in[10];
    const float* b2    = (const float*)d_in[11];
    float* out = (float*)d_out;

    gemm_kernel<<<dim3(24, 16), 256>>>(seq, W1, b1);
    se_kernel<<<M_, 128>>>(seq, Ws, bs, We, be, spos, epos);
    span_kernel<<<dim3(4, 4, 8), 256>>>(spanp, w2, b2, out);
}